// round 2
// baseline (speedup 1.0000x reference)
#include <cuda_runtime.h>
#include <cuda_fp16.h>
#include <cstdint>

#define DI __device__ __forceinline__

// ---------------- problem constants (fixed shapes) ----------------
constexpr int NTOK   = 4096;   // B*S = 2*2048
constexpr int DMODEL = 1024;
constexpr int DFF    = 4096;
constexpr int HH     = 32;

// ---------------- scratch (device globals; no allocs allowed) ----------------
__device__ __align__(16) __half g_xh  [NTOK * DMODEL];      // 8 MB
__device__ __align__(16) __half g_w1ah[DFF  * DMODEL];      // 8 MB
__device__ __align__(16) __half g_w1bh[DFF  * DMODEL];      // 8 MB
__device__ __align__(16) __half g_w2h [DMODEL * DFF];       // 8 MB
__device__ __align__(16) __half g_act [(size_t)NTOK * DFF]; // 32 MB

// ---------------- PTX helpers ----------------
DI uint32_t s2u(const void* p) {
    uint32_t a;
    asm("{ .reg .u64 t; cvta.to.shared.u64 t, %1; cvt.u32.u64 %0, t; }"
        : "=r"(a) : "l"(p));
    return a;
}

#define CP_COMMIT() asm volatile("cp.async.commit_group;" ::: "memory")
#define CP_WAIT_1() asm volatile("cp.async.wait_group 1;" ::: "memory")
#define CP_WAIT_0() asm volatile("cp.async.wait_group 0;" ::: "memory")

DI void cp16(uint32_t sdst, const void* gsrc) {
    asm volatile("cp.async.cg.shared.global [%0], [%1], 16;"
                 :: "r"(sdst), "l"(__cvta_generic_to_global(gsrc)) : "memory");
}

DI void ldsm4(uint32_t r[4], uint32_t addr) {
    asm volatile("ldmatrix.sync.aligned.m8n8.x4.shared.b16 {%0,%1,%2,%3}, [%4];"
                 : "=r"(r[0]), "=r"(r[1]), "=r"(r[2]), "=r"(r[3]) : "r"(addr));
}

DI void mma16816(float c[4], const uint32_t a[4], uint32_t b0, uint32_t b1) {
    asm volatile(
        "mma.sync.aligned.m16n8k16.row.col.f32.f16.f16.f32 "
        "{%0,%1,%2,%3}, {%4,%5,%6,%7}, {%8,%9}, {%0,%1,%2,%3};"
        : "+f"(c[0]), "+f"(c[1]), "+f"(c[2]), "+f"(c[3])
        : "r"(a[0]), "r"(a[1]), "r"(a[2]), "r"(a[3]), "r"(b0), "r"(b1));
}

// SW128 swizzled address inside a 128-row x 128-byte tile.
// row stride = 128B, chunk = 16B column index (0..7), chunk' = chunk ^ (row & 7)
DI uint32_t tile_addr(uint32_t base, int row, int chunk) {
    return base + row * 128 + (((chunk) ^ (row & 7)) << 4);
}

// Load a 128-row x 64-fp16 (128B/row) tile into SW128-swizzled SMEM via cp.async.
template <int NT>
DI void load_tile(uint32_t sdst, const __half* g, int row0, int col0, int ldk, int tid) {
#pragma unroll
    for (int i = 0; i < 1024 / NT; ++i) {
        int idx = tid + i * NT;
        int r = idx >> 3, c = idx & 7;
        uint32_t off = (uint32_t)(r * 128) + (uint32_t)(((c ^ (r & 7)) << 4));
        cp16(sdst + off, g + (size_t)(row0 + r) * ldk + col0 + c * 8);
    }
}

DI uint32_t pack2(float a, float b) {
    __half2 h = __floats2half2_rn(a, b);
    return reinterpret_cast<uint32_t&>(h);
}

// ---------------- SMEM layouts ----------------
constexpr int G1_STRIDE = 49152;                 // A(16K) + Ba(16K) + Bb(16K) per stage
constexpr int G1_PAR    = 2 * G1_STRIDE;         // 98304
constexpr int SMEM1_TOTAL = G1_PAR + 2048;       // 100352
constexpr int G2_STRIDE = 32768;                 // A(16K) + B(16K)
constexpr int G2_PAR    = 2 * G2_STRIDE;         // 65536
constexpr int SMEM2_TOTAL = G2_PAR + 512;        // 66048

// =====================================================================
// Kernel 0: fp32 -> fp16 conversion of x, W1a, W1b, W2
// =====================================================================
__global__ void __launch_bounds__(256) convert_kernel(
    const float4* __restrict__ x, const float4* __restrict__ w1a,
    const float4* __restrict__ w1b, const float4* __restrict__ w2)
{
    int i = blockIdx.x * 256 + threadIdx.x;   // 4096*256 = 2^20 float4s per array
    float4 v;
    v = x[i];   ((uint2*)g_xh)[i]   = make_uint2(pack2(v.x, v.y), pack2(v.z, v.w));
    v = w1a[i]; ((uint2*)g_w1ah)[i] = make_uint2(pack2(v.x, v.y), pack2(v.z, v.w));
    v = w1b[i]; ((uint2*)g_w1bh)[i] = make_uint2(pack2(v.x, v.y), pack2(v.z, v.w));
    v = w2[i];  ((uint2*)g_w2h)[i]  = make_uint2(pack2(v.x, v.y), pack2(v.z, v.w));
}

// =====================================================================
// Kernel 1: fused GEMM1 (a & b projections) + InnerNet -> fp16 act
// CTA tile 128 tokens x 128 ff. 512 threads, 4x4 warp grid, 32x32 warp tiles.
// =====================================================================
__global__ void __launch_bounds__(512) gemm1_kernel(
    const float* __restrict__ b1a, const float* __restrict__ b1b,
    const float* __restrict__ wi1, const float* __restrict__ bi1,
    const float* __restrict__ wi2, const float* __restrict__ bi2)
{
    extern __shared__ char smem[];
    uint32_t sb = s2u(smem);
    int tid = threadIdx.x, lane = tid & 31, wid = tid >> 5;
    int wm = wid >> 2, wn = wid & 3;          // 4x4 warp grid
    int f0 = blockIdx.x * 128;                // d_ff tile
    int m0 = blockIdx.y * 128;                // token tile

    // small params -> smem
    float* sp = (float*)(smem + G1_PAR);
    if (tid < 128) { sp[tid] = b1a[f0 + tid]; sp[128 + tid] = b1b[f0 + tid]; }
    else if (tid < 192) sp[128 + tid] = wi1[tid - 128];          // [256..319]
    else if (tid < 224) { sp[128 + tid] = bi1[tid - 192];        // [320..351]
                          sp[160 + tid] = wi2[tid - 192]; }      // [352..383]
    else if (tid == 224) sp[384] = bi2[0];
    // NOTE: indices above: bi1 at sp[320..351], wi2 at sp[352..383]

    // prefetch K-chunk 0 into stage 0
    load_tile<512>(sb,         g_xh,   m0, 0, DMODEL, tid);
    load_tile<512>(sb + 16384, g_w1ah, f0, 0, DMODEL, tid);
    load_tile<512>(sb + 32768, g_w1bh, f0, 0, DMODEL, tid);
    CP_COMMIT();

    float acca[2][4][4], accb[2][4][4];
#pragma unroll
    for (int i = 0; i < 2; ++i)
#pragma unroll
        for (int j = 0; j < 4; ++j)
#pragma unroll
            for (int e = 0; e < 4; ++e) { acca[i][j][e] = 0.f; accb[i][j][e] = 0.f; }

    const int lr = lane & 15, lc = lane >> 4;
    constexpr int NCH = DMODEL / 64;          // 16 K-chunks
    for (int c = 0; c < NCH; ++c) {
        int buf = c & 1;
        if (c + 1 < NCH) {
            uint32_t nb = sb + (buf ^ 1) * G1_STRIDE;
            int col = (c + 1) * 64;
            load_tile<512>(nb,         g_xh,   m0, col, DMODEL, tid);
            load_tile<512>(nb + 16384, g_w1ah, f0, col, DMODEL, tid);
            load_tile<512>(nb + 32768, g_w1bh, f0, col, DMODEL, tid);
            CP_COMMIT();
            CP_WAIT_1();
        } else {
            CP_WAIT_0();
        }
        __syncthreads();

        uint32_t ab  = sb + buf * G1_STRIDE;
        uint32_t bab = ab + 16384;
        uint32_t bbb = ab + 32768;
#pragma unroll
        for (int ks = 0; ks < 4; ++ks) {
            uint32_t afr[2][4], bfa[2][4], bfb[2][4];
#pragma unroll
            for (int i = 0; i < 2; ++i)
                ldsm4(afr[i], tile_addr(ab, wm * 32 + i * 16 + lr, ks * 2 + lc));
#pragma unroll
            for (int q = 0; q < 2; ++q) {
                ldsm4(bfa[q], tile_addr(bab, wn * 32 + q * 16 + lr, ks * 2 + lc));
                ldsm4(bfb[q], tile_addr(bbb, wn * 32 + q * 16 + lr, ks * 2 + lc));
            }
#pragma unroll
            for (int i = 0; i < 2; ++i)
#pragma unroll
                for (int j = 0; j < 4; ++j) {
                    int q = j >> 1, s = j & 1;
                    mma16816(acca[i][j], afr[i], bfa[q][s], bfa[q][s + 2]);
                    mma16816(accb[i][j], afr[i], bfb[q][s], bfb[q][s + 2]);
                }
        }
        __syncthreads();
    }

    // ---- epilogue: bias + InnerNet, write fp16 act ----
    const float bi2v = sp[384];
    const int g = lane >> 2, tg = lane & 3;
#pragma unroll
    for (int i = 0; i < 2; ++i) {
        float av[16], bv[16], acc[16];
#pragma unroll
        for (int j = 0; j < 4; ++j) {
            int cb = wn * 32 + j * 8 + tg * 2;
#pragma unroll
            for (int e = 0; e < 4; ++e) {
                int idx = j * 4 + e;
                int col = cb + (e & 1);
                av[idx]  = acca[i][j][e] + sp[col];
                bv[idx]  = accb[i][j][e] + sp[128 + col];
                acc[idx] = bi2v;
            }
        }
#pragma unroll 1
        for (int h = 0; h < HH; ++h) {
            float w0 = sp[256 + 2 * h], w1 = sp[257 + 2 * h];
            float cb = sp[320 + h],     vv = sp[352 + h];
#pragma unroll
            for (int idx = 0; idx < 16; ++idx) {
                float t = fmaf(av[idx], w0, cb);
                t = fmaf(bv[idx], w1, t);
                t = fmaxf(t, 0.0f);
                acc[idx] = fmaf(t, vv, acc[idx]);
            }
        }
        int rowg = m0 + wm * 32 + i * 16 + g;
#pragma unroll
        for (int j = 0; j < 4; ++j) {
            int col = f0 + wn * 32 + j * 8 + tg * 2;
            *(uint32_t*)&g_act[(size_t)rowg * DFF + col]       = pack2(acc[j * 4 + 0], acc[j * 4 + 1]);
            *(uint32_t*)&g_act[(size_t)(rowg + 8) * DFF + col] = pack2(acc[j * 4 + 2], acc[j * 4 + 3]);
        }
    }
}

// =====================================================================
// Kernel 2: out = act @ W2^T + b2   (fp16 in, fp32 out)
// CTA tile 128 tokens x 128 d_model. 256 threads, 2x4 warp grid, 64x32 warp tiles.
// =====================================================================
__global__ void __launch_bounds__(256) gemm2_kernel(
    const float* __restrict__ b2, float* __restrict__ out)
{
    extern __shared__ char smem[];
    uint32_t sb = s2u(smem);
    int tid = threadIdx.x, lane = tid & 31, wid = tid >> 5;
    int wm = wid >> 2, wn = wid & 3;          // 2x4 warp grid
    int n0 = blockIdx.x * 128;                // d_model tile
    int m0 = blockIdx.y * 128;                // token tile

    float* sp = (float*)(smem + G2_PAR);
    if (tid < 128) sp[tid] = b2[n0 + tid];

    load_tile<256>(sb,         g_act, m0, 0, DFF, tid);
    load_tile<256>(sb + 16384, g_w2h, n0, 0, DFF, tid);
    CP_COMMIT();

    float acc[4][4][4];
#pragma unroll
    for (int i = 0; i < 4; ++i)
#pragma unroll
        for (int j = 0; j < 4; ++j)
#pragma unroll
            for (int e = 0; e < 4; ++e) acc[i][j][e] = 0.f;

    const int lr = lane & 15, lc = lane >> 4;
    constexpr int NCH = DFF / 64;             // 64 K-chunks
    for (int c = 0; c < NCH; ++c) {
        int buf = c & 1;
        if (c + 1 < NCH) {
            uint32_t nb = sb + (buf ^ 1) * G2_STRIDE;
            int col = (c + 1) * 64;
            load_tile<256>(nb,         g_act, m0, col, DFF, tid);
            load_tile<256>(nb + 16384, g_w2h, n0, col, DFF, tid);
            CP_COMMIT();
            CP_WAIT_1();
        } else {
            CP_WAIT_0();
        }
        __syncthreads();

        uint32_t ab = sb + buf * G2_STRIDE;
        uint32_t bb = ab + 16384;
#pragma unroll
        for (int ks = 0; ks < 4; ++ks) {
            uint32_t afr[4][4], bf[2][4];
#pragma unroll
            for (int i = 0; i < 4; ++i)
                ldsm4(afr[i], tile_addr(ab, wm * 64 + i * 16 + lr, ks * 2 + lc));
#pragma unroll
            for (int q = 0; q < 2; ++q)
                ldsm4(bf[q], tile_addr(bb, wn * 32 + q * 16 + lr, ks * 2 + lc));
#pragma unroll
            for (int i = 0; i < 4; ++i)
#pragma unroll
                for (int j = 0; j < 4; ++j) {
                    int q = j >> 1, s = j & 1;
                    mma16816(acc[i][j], afr[i], bf[q][s], bf[q][s + 2]);
                }
        }
        __syncthreads();
    }

    const int g = lane >> 2, tg = lane & 3;
#pragma unroll
    for (int i = 0; i < 4; ++i) {
        int rowg = m0 + wm * 64 + i * 16 + g;
#pragma unroll
        for (int j = 0; j < 4; ++j) {
            int cb = wn * 32 + j * 8 + tg * 2;
            float2 v0 = make_float2(acc[i][j][0] + sp[cb], acc[i][j][1] + sp[cb + 1]);
            float2 v1 = make_float2(acc[i][j][2] + sp[cb], acc[i][j][3] + sp[cb + 1]);
            *(float2*)&out[(size_t)rowg * DMODEL + n0 + cb]       = v0;
            *(float2*)&out[(size_t)(rowg + 8) * DMODEL + n0 + cb] = v1;
        }
    }
}

// =====================================================================
// launch
// =====================================================================
extern "C" void kernel_launch(void* const* d_in, const int* in_sizes, int n_in,
                              void* d_out, int out_size)
{
    const float* x   = (const float*)d_in[0];
    const float* W1a = (const float*)d_in[1];
    const float* b1a = (const float*)d_in[2];
    const float* W1b = (const float*)d_in[3];
    const float* b1b = (const float*)d_in[4];
    const float* Wi1 = (const float*)d_in[5];
    const float* bi1 = (const float*)d_in[6];
    const float* Wi2 = (const float*)d_in[7];
    const float* bi2 = (const float*)d_in[8];
    const float* W2  = (const float*)d_in[9];
    const float* b2  = (const float*)d_in[10];
    float* out = (float*)d_out;

    static bool attr_done = false;
    if (!attr_done) {
        cudaFuncSetAttribute(gemm1_kernel, cudaFuncAttributeMaxDynamicSharedMemorySize, SMEM1_TOTAL);
        cudaFuncSetAttribute(gemm2_kernel, cudaFuncAttributeMaxDynamicSharedMemorySize, SMEM2_TOTAL);
        attr_done = true;
    }

    convert_kernel<<<4096, 256>>>((const float4*)x, (const float4*)W1a,
                                  (const float4*)W1b, (const float4*)W2);
    gemm1_kernel<<<dim3(DFF / 128, NTOK / 128), 512, SMEM1_TOTAL>>>(b1a, b1b, Wi1, bi1, Wi2, bi2);
    gemm2_kernel<<<dim3(DMODEL / 128, NTOK / 128), 256, SMEM2_TOTAL>>>(b2, out);
}